// round 13
// baseline (speedup 1.0000x reference)
#include <cuda_runtime.h>
#include <cstdint>

#define BS 128
#define NC 1024
#define U  512
#define F  512
#define FOURU 2048
#define KTOT 1024
#define NSLICE 8
#define KSLICE 128

typedef unsigned int  uint;
typedef unsigned short ushort;

// ---------------- scratch (no allocations allowed) ----------------
__device__ float  g_h0[BS * U];
__device__ float  g_c0[BS * U];
__device__ int    g_idx[BS];
__device__ float  g_zpart[NSLICE][BS * FOURU];    // partial z per K-slice
__device__ float  g_z[BS * FOURU];                // reduced z (+bias)
__device__ ushort g_Ah[BS * KTOT];                // A=[x|h0] hi plane, [m][k]
__device__ ushort g_Al[BS * KTOT];                // lo plane

// ---------------- helpers ----------------
__device__ __forceinline__ ushort f2bf(float a) {
    ushort u;
    asm("cvt.rn.bf16.f32 %0, %1;" : "=h"(u) : "f"(a));
    return u;
}
__device__ __forceinline__ float bf2f(ushort u) {
    float f;
    asm("cvt.f32.bf16 %0, %1;" : "=f"(f) : "h"(u));
    return f;
}
// exact float max via signed/unsigned integer atomics (single HW op, no CAS loop)
__device__ __forceinline__ void atomicMaxFloat(float* addr, float val) {
    if (val >= 0.0f) atomicMax((int*)addr, __float_as_int(val));
    else             atomicMin((uint*)addr, __float_as_uint(val));
}
__device__ __forceinline__ float fsig(float x) {
    float e, r;
    asm("ex2.approx.ftz.f32 %0, %1;" : "=f"(e) : "f"(-x * 1.4426950408889634f));
    asm("rcp.approx.ftz.f32 %0, %1;" : "=f"(r) : "f"(1.0f + e));
    return r;
}
__device__ __forceinline__ float ftanh_fast(float x) {
    return 2.0f * fsig(2.0f * x) - 1.0f;
}
__device__ __forceinline__ void mma16816(float* d, uint a0, uint a1, uint a2, uint a3,
                                         uint b0, uint b1) {
    asm volatile(
        "mma.sync.aligned.m16n8k16.row.col.f32.bf16.bf16.f32 "
        "{%0,%1,%2,%3}, {%4,%5,%6,%7}, {%8,%9}, {%0,%1,%2,%3};"
        : "+f"(d[0]), "+f"(d[1]), "+f"(d[2]), "+f"(d[3])
        : "r"(a0), "r"(a1), "r"(a2), "r"(a3), "r"(b0), "r"(b1));
}

// ---------------- K1: argmax + gather + convert A row to bf16 planes ----------
__global__ void k_argmax_gather(const float* __restrict__ logits,
                                const float* __restrict__ x,
                                const float* __restrict__ h_states,
                                const float* __restrict__ c_states) {
    const int b = blockIdx.x;
    const int t = threadIdx.x;                 // 256 threads
    const float* row = logits + b * NC;

    float best = -3.4e38f;
    int   bi   = 0x7fffffff;
#pragma unroll
    for (int j = 0; j < NC; j += 256) {
        float v = row[j + t];
        int   i = j + t;
        if (v > best || (v == best && i < bi)) { best = v; bi = i; }
    }
#pragma unroll
    for (int off = 16; off; off >>= 1) {
        float ov = __shfl_down_sync(0xffffffffu, best, off);
        int   oi = __shfl_down_sync(0xffffffffu, bi,   off);
        if (ov > best || (ov == best && oi < bi)) { best = ov; bi = oi; }
    }
    __shared__ float sv[8];
    __shared__ int   si[8];
    __shared__ int   s_idx;
    if ((t & 31) == 0) { sv[t >> 5] = best; si[t >> 5] = bi; }
    __syncthreads();
    if (t == 0) {
        best = sv[0]; bi = si[0];
#pragma unroll
        for (int w = 1; w < 8; ++w)
            if (sv[w] > best || (sv[w] == best && si[w] < bi)) { best = sv[w]; bi = si[w]; }
        s_idx = bi;
        g_idx[b] = bi;
    }
    __syncthreads();
    const int idx = s_idx;

    // gather states
    const float4* hs = (const float4*)(h_states + idx * U);
    const float4* cs = (const float4*)(c_states + idx * U);
    float4* hd = (float4*)(g_h0 + b * U);
    float4* cd = (float4*)(g_c0 + b * U);
    if (t < U / 4) { hd[t] = hs[t]; cd[t] = cs[t]; }

    // convert A row b: x part [0..511], h0 part [512..1023]
    {
        float2 xv = *(const float2*)(x + b * F + 2 * t);
        float2 hv = *(const float2*)(h_states + idx * U + 2 * t);
        ushort xh0 = f2bf(xv.x), xh1 = f2bf(xv.y);
        ushort xl0 = f2bf(xv.x - bf2f(xh0)), xl1 = f2bf(xv.y - bf2f(xh1));
        ushort hh0 = f2bf(hv.x), hh1 = f2bf(hv.y);
        ushort hl0 = f2bf(hv.x - bf2f(hh0)), hl1 = f2bf(hv.y - bf2f(hh1));
        *(uint*)&g_Ah[b * KTOT + 2 * t]       = (uint)xh0 | ((uint)xh1 << 16);
        *(uint*)&g_Al[b * KTOT + 2 * t]       = (uint)xl0 | ((uint)xl1 << 16);
        *(uint*)&g_Ah[b * KTOT + 512 + 2 * t] = (uint)hh0 | ((uint)hh1 << 16);
        *(uint*)&g_Al[b * KTOT + 512 + 2 * t] = (uint)hl0 | ((uint)hl1 << 16);
    }
}

// ---------------- K2: copy states into output (base for scatter-max) ----------------
__global__ void k_copy_states(const float* __restrict__ h_states,
                              const float* __restrict__ c_states,
                              float* __restrict__ out_newh,
                              float* __restrict__ out_newc) {
    const int i = blockIdx.x * 256 + threadIdx.x;   // 0..32767
    const int Q = NC * U / 16;                      // 32768 float4s per quarter
    float4 h1 = ((const float4*)h_states)[i];
    float4 h2 = ((const float4*)h_states)[i + Q];
    float4 h3 = ((const float4*)h_states)[i + 2 * Q];
    float4 h4 = ((const float4*)h_states)[i + 3 * Q];
    float4 c1 = ((const float4*)c_states)[i];
    float4 c2 = ((const float4*)c_states)[i + Q];
    float4 c3 = ((const float4*)c_states)[i + 2 * Q];
    float4 c4 = ((const float4*)c_states)[i + 3 * Q];
    ((float4*)out_newh)[i]         = h1;
    ((float4*)out_newh)[i + Q]     = h2;
    ((float4*)out_newh)[i + 2 * Q] = h3;
    ((float4*)out_newh)[i + 3 * Q] = h4;
    ((float4*)out_newc)[i]         = c1;
    ((float4*)out_newc)[i + Q]     = c2;
    ((float4*)out_newc)[i + 2 * Q] = c3;
    ((float4*)out_newc)[i + 3 * Q] = c4;
}

// ---------------- K3: tensor-core GEMM, 3-term bf16 split, tile M128xN64 ----------
// grid(32, 8): x = N-tile (64 cols), y = K-slice (128 rows of combined K).
// Block 256 thr = 8 warps (4M x 2N), warp tile M32 x N32, 8 iters of k16.
#define RSTRIDE 24   // A row stride in ushorts (48 B)
#define BSTRU 12     // B row stride in uints (48 B)

__global__ __launch_bounds__(256, 2) void k_gemm_mma(const float* __restrict__ kernelW,
                                                     const float* __restrict__ recW) {
    __shared__ ushort sAh[2][128 * RSTRIDE];
    __shared__ ushort sAl[2][128 * RSTRIDE];
    __shared__ uint   sBh[2][64 * BSTRU];
    __shared__ uint   sBl[2][64 * BSTRU];

    const int t    = threadIdx.x;
    const int wid  = t >> 5;
    const int lane = t & 31;
    const int g    = lane >> 2;
    const int tq   = lane & 3;
    const int warp_m = wid >> 1;      // 0..3  (M 32 each)
    const int warp_n = wid & 1;       // 0..1  (N 32 each)

    const int n_blk  = blockIdx.x * 64;
    const int kslice = blockIdx.y;                 // 0..7
    const int kbase  = kslice * KSLICE;            // offset in combined K
    float* __restrict__ Zout = g_zpart[kslice];
    const float* __restrict__ Bsl = (kslice < 4) ? kernelW : recW;  // [512][2048]
    const int koff = (kslice & 3) * KSLICE;        // row offset within that weight

    // A staging: rA = row, hA selects 8-ushort half of the k16 chunk
    const int rA = t >> 1;            // 0..127
    const int hA = t & 1;
    const ushort* pAh = g_Ah + rA * KTOT + kbase + hA * 8;
    const ushort* pAl = g_Al + rA * KTOT + kbase + hA * 8;

    // B staging: coalesced in n (t&63), each thread loads 4 floats:
    // k rows {2kp, 2kp+1, 2kp+8, 2kp+9} at column n.
    const int nB = t & 63;
    const int kp = t >> 6;            // 0..3
    const float* pB = Bsl + (koff + 2 * kp) * FOURU + n_blk + nB;

    float acc[2][4][4];
#pragma unroll
    for (int i = 0; i < 2; ++i)
#pragma unroll
        for (int j = 0; j < 4; ++j)
#pragma unroll
            for (int q = 0; q < 4; ++q) acc[i][j][q] = 0.f;

    uint4 cAh = *(const uint4*)pAh;
    uint4 cAl = *(const uint4*)pAl;
    float b00 = pB[0];
    float b01 = pB[FOURU];
    float b10 = pB[8 * FOURU];
    float b11 = pB[9 * FOURU];

    for (int s = 0; s < 8; ++s) {
        const int buf = s & 1;
        *(uint4*)&sAh[buf][rA * RSTRIDE + hA * 8] = cAh;
        *(uint4*)&sAl[buf][rA * RSTRIDE + hA * 8] = cAl;
        {
            ushort h0 = f2bf(b00), h1 = f2bf(b01);
            ushort l0 = f2bf(b00 - bf2f(h0)), l1 = f2bf(b01 - bf2f(h1));
            sBh[buf][nB * BSTRU + kp] = (uint)h0 | ((uint)h1 << 16);
            sBl[buf][nB * BSTRU + kp] = (uint)l0 | ((uint)l1 << 16);
            h0 = f2bf(b10); h1 = f2bf(b11);
            l0 = f2bf(b10 - bf2f(h0)); l1 = f2bf(b11 - bf2f(h1));
            sBh[buf][nB * BSTRU + kp + 4] = (uint)h0 | ((uint)h1 << 16);
            sBl[buf][nB * BSTRU + kp + 4] = (uint)l0 | ((uint)l1 << 16);
        }
        __syncthreads();

        if (s < 7) {
            cAh = *(const uint4*)(pAh + (s + 1) * 16);
            cAl = *(const uint4*)(pAl + (s + 1) * 16);
            const float* nBp = pB + (s + 1) * 16 * FOURU;
            b00 = nBp[0];
            b01 = nBp[FOURU];
            b10 = nBp[8 * FOURU];
            b11 = nBp[9 * FOURU];
        }

        // B fragments: 4 n-subtiles x (hi, lo)
        uint bh[4][2], bl[4][2];
#pragma unroll
        for (int nt = 0; nt < 4; ++nt) {
            const int nrow = warp_n * 32 + nt * 8 + g;
            const uint* qh = &sBh[buf][nrow * BSTRU];
            const uint* ql = &sBl[buf][nrow * BSTRU];
            bh[nt][0] = qh[tq];  bh[nt][1] = qh[tq + 4];
            bl[nt][0] = ql[tq];  bl[nt][1] = ql[tq + 4];
        }

#pragma unroll
        for (int mt = 0; mt < 2; ++mt) {
            const int rb = warp_m * 32 + mt * 16;
            const uint* r0h = (const uint*)&sAh[buf][(rb + g) * RSTRIDE];
            const uint* r1h = (const uint*)&sAh[buf][(rb + g + 8) * RSTRIDE];
            const uint* r0l = (const uint*)&sAl[buf][(rb + g) * RSTRIDE];
            const uint* r1l = (const uint*)&sAl[buf][(rb + g + 8) * RSTRIDE];
            uint ah0 = r0h[tq], ah1 = r1h[tq], ah2 = r0h[tq + 4], ah3 = r1h[tq + 4];
            uint al0 = r0l[tq], al1 = r1l[tq], al2 = r0l[tq + 4], al3 = r1l[tq + 4];
#pragma unroll
            for (int nt = 0; nt < 4; ++nt) {
                mma16816(acc[mt][nt], ah0, ah1, ah2, ah3, bh[nt][0], bh[nt][1]);
                mma16816(acc[mt][nt], al0, al1, al2, al3, bh[nt][0], bh[nt][1]);
                mma16816(acc[mt][nt], ah0, ah1, ah2, ah3, bl[nt][0], bl[nt][1]);
            }
        }
        __syncthreads();
    }

#pragma unroll
    for (int mt = 0; mt < 2; ++mt)
#pragma unroll
        for (int nt = 0; nt < 4; ++nt) {
            const int m0 = warp_m * 32 + mt * 16 + g;
            const int nc = n_blk + warp_n * 32 + nt * 8 + 2 * tq;
            *(float2*)(Zout + m0 * FOURU + nc)       = make_float2(acc[mt][nt][0], acc[mt][nt][1]);
            *(float2*)(Zout + (m0 + 8) * FOURU + nc) = make_float2(acc[mt][nt][2], acc[mt][nt][3]);
        }
}

// ---------------- K4a: reduce 8 zpart planes + bias -> g_z (float4, MLP=8) -------
__global__ void k_reduce_z(const float* __restrict__ bias) {
    const int i4 = (blockIdx.x * 256 + threadIdx.x) * 4;   // 256 blocks x 256 thr
    float4 s = *(const float4*)&g_zpart[0][i4];
#pragma unroll
    for (int p = 1; p < NSLICE; ++p) {
        float4 v = *(const float4*)&g_zpart[p][i4];
        s.x += v.x; s.y += v.y; s.z += v.z; s.w += v.w;
    }
    float4 bv = *(const float4*)&bias[i4 & (FOURU - 1)];
    s.x += bv.x; s.y += bv.y; s.z += bv.z; s.w += bv.w;
    *(float4*)&g_z[i4] = s;
}

// ---------------- K4b: gates + LSTM cell + scatter-max (1 unit / thread) ---------
__global__ void k_gates_scatter(float* __restrict__ out_h,
                                float* __restrict__ out_newh,
                                float* __restrict__ out_newc) {
    const int i = blockIdx.x * 256 + threadIdx.x;  // 0 .. BS*U-1
    const int b = i >> 9;            // / U
    const int u = i & (U - 1);

    const float* z = g_z + b * FOURU + u;
    const float zi = z[0];
    const float zf = z[U];
    const float zg = z[2 * U];
    const float zo = z[3 * U];

    float ig = fsig(zi);
    float fg = fsig(zf);
    float gg = ftanh_fast(zg);
    float og = fsig(zo);

    float c0 = g_c0[i];
    float c  = fg * c0 + ig * gg;
    float h  = og * ftanh_fast(c);

    out_h[i] = h;

    const int cls = g_idx[b];
    atomicMaxFloat(&out_newh[cls * U + u], h);
    atomicMaxFloat(&out_newc[cls * U + u], c);
}

// ---------------- launch ----------------
extern "C" void kernel_launch(void* const* d_in, const int* in_sizes, int n_in,
                              void* d_out, int out_size) {
    const float* x        = (const float*)d_in[0];
    const float* logits   = (const float*)d_in[1];
    const float* h_states = (const float*)d_in[2];
    const float* c_states = (const float*)d_in[3];
    const float* kernelW  = (const float*)d_in[4];
    const float* recW     = (const float*)d_in[5];
    const float* bias     = (const float*)d_in[6];

    float* out      = (float*)d_out;
    float* out_h    = out;                    // (128, 512)
    float* out_newh = out + BS * U;           // (1024, 512)
    float* out_newc = out + BS * U + NC * U;  // (1024, 512)

    k_argmax_gather<<<BS, 256>>>(logits, x, h_states, c_states);
    k_copy_states<<<128, 256>>>(h_states, c_states, out_newh, out_newc);
    {
        dim3 gg(FOURU / 64, NSLICE);          // (32, 8) = 256 blocks
        k_gemm_mma<<<gg, 256>>>(kernelW, recW);
    }
    k_reduce_z<<<BS * FOURU / (256 * 4), 256>>>(bias);      // 256 blocks
    k_gates_scatter<<<(BS * U) / 256, 256>>>(out_h, out_newh, out_newc);
}

// round 14
// speedup vs baseline: 1.1017x; 1.1017x over previous
#include <cuda_runtime.h>
#include <cstdint>

#define BS 128
#define NC 1024
#define U  512
#define F  512
#define FOURU 2048
#define KTOT 1024
#define NSLICE 8
#define KSLICE 128

typedef unsigned int  uint;
typedef unsigned short ushort;

// ---------------- scratch (no allocations allowed) ----------------
__device__ float  g_h0[BS * U];
__device__ float  g_c0[BS * U];
__device__ int    g_idx[BS];
__device__ float  g_z[BS * FOURU];                // z accumulator (bias-init, atomics)
__device__ ushort g_Ah[BS * KTOT];                // A=[x|h0] hi plane, [m][k]
__device__ ushort g_Al[BS * KTOT];                // lo plane

// ---------------- helpers ----------------
__device__ __forceinline__ ushort f2bf(float a) {
    ushort u;
    asm("cvt.rn.bf16.f32 %0, %1;" : "=h"(u) : "f"(a));
    return u;
}
__device__ __forceinline__ float bf2f(ushort u) {
    float f;
    asm("cvt.f32.bf16 %0, %1;" : "=f"(f) : "h"(u));
    return f;
}
// exact float max via signed/unsigned integer atomics (single HW op, no CAS loop)
__device__ __forceinline__ void atomicMaxFloat(float* addr, float val) {
    if (val >= 0.0f) atomicMax((int*)addr, __float_as_int(val));
    else             atomicMin((uint*)addr, __float_as_uint(val));
}
__device__ __forceinline__ float fsig(float x) {
    float e, r;
    asm("ex2.approx.ftz.f32 %0, %1;" : "=f"(e) : "f"(-x * 1.4426950408889634f));
    asm("rcp.approx.ftz.f32 %0, %1;" : "=f"(r) : "f"(1.0f + e));
    return r;
}
__device__ __forceinline__ float ftanh_fast(float x) {
    return 2.0f * fsig(2.0f * x) - 1.0f;
}
__device__ __forceinline__ void mma16816(float* d, uint a0, uint a1, uint a2, uint a3,
                                         uint b0, uint b1) {
    asm volatile(
        "mma.sync.aligned.m16n8k16.row.col.f32.bf16.bf16.f32 "
        "{%0,%1,%2,%3}, {%4,%5,%6,%7}, {%8,%9}, {%0,%1,%2,%3};"
        : "+f"(d[0]), "+f"(d[1]), "+f"(d[2]), "+f"(d[3])
        : "r"(a0), "r"(a1), "r"(a2), "r"(a3), "r"(b0), "r"(b1));
}
// no-return global float2 reduction (REDG)
__device__ __forceinline__ void redAddF2(float* addr, float a, float b) {
    asm volatile("red.global.add.v2.f32 [%0], {%1, %2};"
                 :: "l"(addr), "f"(a), "f"(b) : "memory");
}

// ---------------- K1: argmax + gather + convert A row to bf16 planes ----------
__global__ void k_argmax_gather(const float* __restrict__ logits,
                                const float* __restrict__ x,
                                const float* __restrict__ h_states,
                                const float* __restrict__ c_states) {
    const int b = blockIdx.x;
    const int t = threadIdx.x;                 // 256 threads
    const float* row = logits + b * NC;

    float best = -3.4e38f;
    int   bi   = 0x7fffffff;
#pragma unroll
    for (int j = 0; j < NC; j += 256) {
        float v = row[j + t];
        int   i = j + t;
        if (v > best || (v == best && i < bi)) { best = v; bi = i; }
    }
#pragma unroll
    for (int off = 16; off; off >>= 1) {
        float ov = __shfl_down_sync(0xffffffffu, best, off);
        int   oi = __shfl_down_sync(0xffffffffu, bi,   off);
        if (ov > best || (ov == best && oi < bi)) { best = ov; bi = oi; }
    }
    __shared__ float sv[8];
    __shared__ int   si[8];
    __shared__ int   s_idx;
    if ((t & 31) == 0) { sv[t >> 5] = best; si[t >> 5] = bi; }
    __syncthreads();
    if (t == 0) {
        best = sv[0]; bi = si[0];
#pragma unroll
        for (int w = 1; w < 8; ++w)
            if (sv[w] > best || (sv[w] == best && si[w] < bi)) { best = sv[w]; bi = si[w]; }
        s_idx = bi;
        g_idx[b] = bi;
    }
    __syncthreads();
    const int idx = s_idx;

    // gather states
    const float4* hs = (const float4*)(h_states + idx * U);
    const float4* cs = (const float4*)(c_states + idx * U);
    float4* hd = (float4*)(g_h0 + b * U);
    float4* cd = (float4*)(g_c0 + b * U);
    if (t < U / 4) { hd[t] = hs[t]; cd[t] = cs[t]; }

    // convert A row b: x part [0..511], h0 part [512..1023]
    {
        float2 xv = *(const float2*)(x + b * F + 2 * t);
        float2 hv = *(const float2*)(h_states + idx * U + 2 * t);
        ushort xh0 = f2bf(xv.x), xh1 = f2bf(xv.y);
        ushort xl0 = f2bf(xv.x - bf2f(xh0)), xl1 = f2bf(xv.y - bf2f(xh1));
        ushort hh0 = f2bf(hv.x), hh1 = f2bf(hv.y);
        ushort hl0 = f2bf(hv.x - bf2f(hh0)), hl1 = f2bf(hv.y - bf2f(hh1));
        *(uint*)&g_Ah[b * KTOT + 2 * t]       = (uint)xh0 | ((uint)xh1 << 16);
        *(uint*)&g_Al[b * KTOT + 2 * t]       = (uint)xl0 | ((uint)xl1 << 16);
        *(uint*)&g_Ah[b * KTOT + 512 + 2 * t] = (uint)hh0 | ((uint)hh1 << 16);
        *(uint*)&g_Al[b * KTOT + 512 + 2 * t] = (uint)hl0 | ((uint)hl1 << 16);
    }
}

// ---------------- K2: copy states into output + init g_z with bias --------------
__global__ void k_copy_states(const float* __restrict__ h_states,
                              const float* __restrict__ c_states,
                              const float* __restrict__ bias,
                              float* __restrict__ out_newh,
                              float* __restrict__ out_newc) {
    const int i = blockIdx.x * 256 + threadIdx.x;   // 0..32767
    const int Q = NC * U / 16;                      // 32768 float4s per quarter
    float4 h1 = ((const float4*)h_states)[i];
    float4 h2 = ((const float4*)h_states)[i + Q];
    float4 h3 = ((const float4*)h_states)[i + 2 * Q];
    float4 h4 = ((const float4*)h_states)[i + 3 * Q];
    float4 c1 = ((const float4*)c_states)[i];
    float4 c2 = ((const float4*)c_states)[i + Q];
    float4 c3 = ((const float4*)c_states)[i + 2 * Q];
    float4 c4 = ((const float4*)c_states)[i + 3 * Q];
    ((float4*)out_newh)[i]         = h1;
    ((float4*)out_newh)[i + Q]     = h2;
    ((float4*)out_newh)[i + 2 * Q] = h3;
    ((float4*)out_newh)[i + 3 * Q] = h4;
    ((float4*)out_newc)[i]         = c1;
    ((float4*)out_newc)[i + Q]     = c2;
    ((float4*)out_newc)[i + 2 * Q] = c3;
    ((float4*)out_newc)[i + 3 * Q] = c4;

    // init g_z = bias (broadcast over rows): 65536 float4s, 2 per thread
    const int z0 = i;                               // float4 index
    const int z1 = i + 32768;
    float4 b0 = *(const float4*)&bias[(z0 * 4) & (FOURU - 1)];
    float4 b1 = *(const float4*)&bias[(z1 * 4) & (FOURU - 1)];
    ((float4*)g_z)[z0] = b0;
    ((float4*)g_z)[z1] = b1;
}

// ---------------- K3: tensor-core GEMM, 3-term bf16 split, REDG accumulate ------
// grid(32, 8): x = N-tile (64 cols), y = K-slice (128 rows of combined K).
// Block 256 thr = 8 warps (4M x 2N), warp tile M32 x N32, 8 iters of k16.
#define RSTRIDE 24   // A row stride in ushorts (48 B)
#define BSTRU 12     // B row stride in uints (48 B)

__global__ __launch_bounds__(256, 2) void k_gemm_mma(const float* __restrict__ kernelW,
                                                     const float* __restrict__ recW) {
    __shared__ ushort sAh[2][128 * RSTRIDE];
    __shared__ ushort sAl[2][128 * RSTRIDE];
    __shared__ uint   sBh[2][64 * BSTRU];
    __shared__ uint   sBl[2][64 * BSTRU];

    const int t    = threadIdx.x;
    const int wid  = t >> 5;
    const int lane = t & 31;
    const int g    = lane >> 2;
    const int tq   = lane & 3;
    const int warp_m = wid >> 1;      // 0..3  (M 32 each)
    const int warp_n = wid & 1;       // 0..1  (N 32 each)

    const int n_blk  = blockIdx.x * 64;
    const int kslice = blockIdx.y;                 // 0..7
    const int kbase  = kslice * KSLICE;            // offset in combined K
    const float* __restrict__ Bsl = (kslice < 4) ? kernelW : recW;  // [512][2048]
    const int koff = (kslice & 3) * KSLICE;        // row offset within that weight

    // A staging: rA = row, hA selects 8-ushort half of the k16 chunk
    const int rA = t >> 1;            // 0..127
    const int hA = t & 1;
    const ushort* pAh = g_Ah + rA * KTOT + kbase + hA * 8;
    const ushort* pAl = g_Al + rA * KTOT + kbase + hA * 8;

    // B staging: coalesced in n (t&63), each thread loads 4 floats:
    // k rows {2kp, 2kp+1, 2kp+8, 2kp+9} at column n.
    const int nB = t & 63;
    const int kp = t >> 6;            // 0..3
    const float* pB = Bsl + (koff + 2 * kp) * FOURU + n_blk + nB;

    float acc[2][4][4];
#pragma unroll
    for (int i = 0; i < 2; ++i)
#pragma unroll
        for (int j = 0; j < 4; ++j)
#pragma unroll
            for (int q = 0; q < 4; ++q) acc[i][j][q] = 0.f;

    uint4 cAh = *(const uint4*)pAh;
    uint4 cAl = *(const uint4*)pAl;
    float b00 = pB[0];
    float b01 = pB[FOURU];
    float b10 = pB[8 * FOURU];
    float b11 = pB[9 * FOURU];

    for (int s = 0; s < 8; ++s) {
        const int buf = s & 1;
        *(uint4*)&sAh[buf][rA * RSTRIDE + hA * 8] = cAh;
        *(uint4*)&sAl[buf][rA * RSTRIDE + hA * 8] = cAl;
        {
            ushort h0 = f2bf(b00), h1 = f2bf(b01);
            ushort l0 = f2bf(b00 - bf2f(h0)), l1 = f2bf(b01 - bf2f(h1));
            sBh[buf][nB * BSTRU + kp] = (uint)h0 | ((uint)h1 << 16);
            sBl[buf][nB * BSTRU + kp] = (uint)l0 | ((uint)l1 << 16);
            h0 = f2bf(b10); h1 = f2bf(b11);
            l0 = f2bf(b10 - bf2f(h0)); l1 = f2bf(b11 - bf2f(h1));
            sBh[buf][nB * BSTRU + kp + 4] = (uint)h0 | ((uint)h1 << 16);
            sBl[buf][nB * BSTRU + kp + 4] = (uint)l0 | ((uint)l1 << 16);
        }
        __syncthreads();

        if (s < 7) {
            cAh = *(const uint4*)(pAh + (s + 1) * 16);
            cAl = *(const uint4*)(pAl + (s + 1) * 16);
            const float* nBp = pB + (s + 1) * 16 * FOURU;
            b00 = nBp[0];
            b01 = nBp[FOURU];
            b10 = nBp[8 * FOURU];
            b11 = nBp[9 * FOURU];
        }

        // B fragments: 4 n-subtiles x (hi, lo)
        uint bh[4][2], bl[4][2];
#pragma unroll
        for (int nt = 0; nt < 4; ++nt) {
            const int nrow = warp_n * 32 + nt * 8 + g;
            const uint* qh = &sBh[buf][nrow * BSTRU];
            const uint* ql = &sBl[buf][nrow * BSTRU];
            bh[nt][0] = qh[tq];  bh[nt][1] = qh[tq + 4];
            bl[nt][0] = ql[tq];  bl[nt][1] = ql[tq + 4];
        }

#pragma unroll
        for (int mt = 0; mt < 2; ++mt) {
            const int rb = warp_m * 32 + mt * 16;
            const uint* r0h = (const uint*)&sAh[buf][(rb + g) * RSTRIDE];
            const uint* r1h = (const uint*)&sAh[buf][(rb + g + 8) * RSTRIDE];
            const uint* r0l = (const uint*)&sAl[buf][(rb + g) * RSTRIDE];
            const uint* r1l = (const uint*)&sAl[buf][(rb + g + 8) * RSTRIDE];
            uint ah0 = r0h[tq], ah1 = r1h[tq], ah2 = r0h[tq + 4], ah3 = r1h[tq + 4];
            uint al0 = r0l[tq], al1 = r1l[tq], al2 = r0l[tq + 4], al3 = r1l[tq + 4];
#pragma unroll
            for (int nt = 0; nt < 4; ++nt) {
                mma16816(acc[mt][nt], ah0, ah1, ah2, ah3, bh[nt][0], bh[nt][1]);
                mma16816(acc[mt][nt], al0, al1, al2, al3, bh[nt][0], bh[nt][1]);
                mma16816(acc[mt][nt], ah0, ah1, ah2, ah3, bl[nt][0], bl[nt][1]);
            }
        }
        __syncthreads();
    }

    // epilogue: accumulate into g_z via no-return vector reductions
#pragma unroll
    for (int mt = 0; mt < 2; ++mt)
#pragma unroll
        for (int nt = 0; nt < 4; ++nt) {
            const int m0 = warp_m * 32 + mt * 16 + g;
            const int nc = n_blk + warp_n * 32 + nt * 8 + 2 * tq;
            redAddF2(g_z + m0 * FOURU + nc,       acc[mt][nt][0], acc[mt][nt][1]);
            redAddF2(g_z + (m0 + 8) * FOURU + nc, acc[mt][nt][2], acc[mt][nt][3]);
        }
}

// ---------------- K4: gates + LSTM cell + scatter-max (1 unit / thread) ---------
__global__ void k_gates_scatter(float* __restrict__ out_h,
                                float* __restrict__ out_newh,
                                float* __restrict__ out_newc) {
    const int i = blockIdx.x * 256 + threadIdx.x;  // 0 .. BS*U-1
    const int b = i >> 9;            // / U
    const int u = i & (U - 1);

    const float* z = g_z + b * FOURU + u;
    const float zi = z[0];
    const float zf = z[U];
    const float zg = z[2 * U];
    const float zo = z[3 * U];

    float ig = fsig(zi);
    float fg = fsig(zf);
    float gg = ftanh_fast(zg);
    float og = fsig(zo);

    float c0 = g_c0[i];
    float c  = fg * c0 + ig * gg;
    float h  = og * ftanh_fast(c);

    out_h[i] = h;

    const int cls = g_idx[b];
    atomicMaxFloat(&out_newh[cls * U + u], h);
    atomicMaxFloat(&out_newc[cls * U + u], c);
}

// ---------------- launch ----------------
extern "C" void kernel_launch(void* const* d_in, const int* in_sizes, int n_in,
                              void* d_out, int out_size) {
    const float* x        = (const float*)d_in[0];
    const float* logits   = (const float*)d_in[1];
    const float* h_states = (const float*)d_in[2];
    const float* c_states = (const float*)d_in[3];
    const float* kernelW  = (const float*)d_in[4];
    const float* recW     = (const float*)d_in[5];
    const float* bias     = (const float*)d_in[6];

    float* out      = (float*)d_out;
    float* out_h    = out;                    // (128, 512)
    float* out_newh = out + BS * U;           // (1024, 512)
    float* out_newc = out + BS * U + NC * U;  // (1024, 512)

    k_argmax_gather<<<BS, 256>>>(logits, x, h_states, c_states);
    k_copy_states<<<128, 256>>>(h_states, c_states, bias, out_newh, out_newc);
    {
        dim3 gg(FOURU / 64, NSLICE);          // (32, 8) = 256 blocks
        k_gemm_mma<<<gg, 256>>>(kernelW, recW);
    }
    k_gates_scatter<<<(BS * U) / 256, 256>>>(out_h, out_newh, out_newc);
}